// round 1
// baseline (speedup 1.0000x reference)
#include <cuda_runtime.h>
#include <math.h>

// Problem constants
#define BQ 2
#define SQ 2048
#define DQ 1024
#define HQ 16
#define DHQ 64
#define FQ 4096
#define MQ (BQ*SQ)   // 4096 rows

// ---------------- scratch (device globals; no allocation allowed) ----------------
__device__ float g_u [MQ*DQ];                 // LN1 output
__device__ float g_Q [BQ*HQ*SQ*DHQ];          // [B,H,S,DH]
__device__ float g_Kr[BQ*HQ*DHQ*SQ];          // K in quirky reshaped layout [B,H,DH,S]
__device__ float g_V [BQ*HQ*SQ*DHQ];          // [B,H,S,DH]
__device__ float g_hc[MQ*DQ];                 // heads concat [B,S,H*DH]
__device__ float g_z1[MQ*DQ];
__device__ float g_v1[MQ*DQ];
__device__ float g_v3[MQ*FQ];                 // FFN mid (64MB)

__device__ __forceinline__ float gelu_exact(float x){
    return 0.5f * x * (1.0f + erff(x * 0.70710678118654752f));
}

// ---------------- LayerNorm: one block per row of 1024 ----------------
__global__ __launch_bounds__(256) void ln_kernel(const float* __restrict__ x,
                                                 const float* __restrict__ gamma,
                                                 const float* __restrict__ beta,
                                                 float* __restrict__ out)
{
    int row = blockIdx.x;
    int t = threadIdx.x;
    const float4* xr = (const float4*)(x + (size_t)row * DQ);
    float4 v = xr[t];   // 256 threads * 4 = 1024 exactly
    float s  = v.x + v.y + v.z + v.w;
    float s2 = v.x*v.x + v.y*v.y + v.z*v.z + v.w*v.w;
    #pragma unroll
    for (int off = 16; off; off >>= 1){
        s  += __shfl_xor_sync(0xffffffffu, s,  off);
        s2 += __shfl_xor_sync(0xffffffffu, s2, off);
    }
    __shared__ float sm[8], sm2[8];
    int w = t >> 5, lane = t & 31;
    if (!lane){ sm[w] = s; sm2[w] = s2; }
    __syncthreads();
    if (t == 0){
        float a = 0.f, b = 0.f;
        #pragma unroll
        for (int i = 0; i < 8; i++){ a += sm[i]; b += sm2[i]; }
        sm[0] = a; sm2[0] = b;
    }
    __syncthreads();
    float mu  = sm[0]  * (1.0f / DQ);
    float var = sm2[0] * (1.0f / DQ) - mu * mu;
    float inv = rsqrtf(var + 1e-5f);
    float4 g  = ((const float4*)gamma)[t];
    float4 be = ((const float4*)beta)[t];
    float4 o;
    o.x = (v.x - mu) * inv * g.x + be.x;
    o.y = (v.y - mu) * inv * g.y + be.y;
    o.z = (v.z - mu) * inv * g.z + be.z;
    o.w = (v.w - mu) * inv * g.w + be.w;
    ((float4*)(out + (size_t)row * DQ))[t] = o;
}

// ---------------- generic SGEMM: C = A(MxK) * B, 128x128x16 tiles, 8x8 microtile ----------------
// Btrans=1: B is [N,K] row-major (use B^T).  Btrans=0: B is [K,N] row-major.
// mode: 0 plain | 1 +resid | 2 gelu(acc+bias) | 3 acc+bias+resid
//       4 scatter to [B,H,S,DH] (Q/V) | 5 scatter to quirky K_r [B,H,DH,S]
__global__ __launch_bounds__(256) void sgemm_kernel(
    const float* __restrict__ A, const float* __restrict__ Bm,
    float* __restrict__ C, int Mdim, int Ndim, int Kdim,
    int Btrans, int mode,
    const float* __restrict__ bias, const float* __restrict__ resid)
{
    __shared__ float As[16][128];
    __shared__ float Bs[16][128];
    int tid = threadIdx.x;
    int bm = blockIdx.y * 128, bn = blockIdx.x * 128;
    int ty = tid >> 4, tx = tid & 15;

    int lr  = tid >> 2;   // 0..63 (row within half-tile for A / NT-B loads)
    int lc4 = tid & 3;    // float4 index within 16-wide k slab
    int br  = tid >> 4;   // 0..15 (k-row for NN-B loads)
    int bc4 = tid & 15;   // float4 col index

    float4 pa0, pa1, pb0, pb1;
    {
        const float* Ap = A + (size_t)(bm + lr) * Kdim + lc4 * 4;
        pa0 = *(const float4*)Ap;
        pa1 = *(const float4*)(Ap + (size_t)64 * Kdim);
        if (Btrans){
            const float* Bp = Bm + (size_t)(bn + lr) * Kdim + lc4 * 4;
            pb0 = *(const float4*)Bp;
            pb1 = *(const float4*)(Bp + (size_t)64 * Kdim);
        } else {
            const float* Bp = Bm + (size_t)br * Ndim + bn + bc4 * 4;
            pb0 = *(const float4*)Bp;
            pb1 = *(const float4*)(Bp + 64);
        }
    }

    float acc[8][8];
    #pragma unroll
    for (int i = 0; i < 8; i++)
        #pragma unroll
        for (int j = 0; j < 8; j++) acc[i][j] = 0.f;

    int ntiles = Kdim >> 4;
    for (int t = 0; t < ntiles; t++){
        // commit prefetched tile to smem
        As[lc4*4+0][lr] = pa0.x; As[lc4*4+1][lr] = pa0.y;
        As[lc4*4+2][lr] = pa0.z; As[lc4*4+3][lr] = pa0.w;
        As[lc4*4+0][lr+64] = pa1.x; As[lc4*4+1][lr+64] = pa1.y;
        As[lc4*4+2][lr+64] = pa1.z; As[lc4*4+3][lr+64] = pa1.w;
        if (Btrans){
            Bs[lc4*4+0][lr] = pb0.x; Bs[lc4*4+1][lr] = pb0.y;
            Bs[lc4*4+2][lr] = pb0.z; Bs[lc4*4+3][lr] = pb0.w;
            Bs[lc4*4+0][lr+64] = pb1.x; Bs[lc4*4+1][lr+64] = pb1.y;
            Bs[lc4*4+2][lr+64] = pb1.z; Bs[lc4*4+3][lr+64] = pb1.w;
        } else {
            *(float4*)&Bs[br][bc4*4]      = pb0;
            *(float4*)&Bs[br][bc4*4 + 64] = pb1;
        }
        __syncthreads();

        if (t + 1 < ntiles){
            int k0 = (t + 1) << 4;
            const float* Ap = A + (size_t)(bm + lr) * Kdim + k0 + lc4 * 4;
            pa0 = *(const float4*)Ap;
            pa1 = *(const float4*)(Ap + (size_t)64 * Kdim);
            if (Btrans){
                const float* Bp = Bm + (size_t)(bn + lr) * Kdim + k0 + lc4 * 4;
                pb0 = *(const float4*)Bp;
                pb1 = *(const float4*)(Bp + (size_t)64 * Kdim);
            } else {
                const float* Bp = Bm + (size_t)(br + k0) * Ndim + bn + bc4 * 4;
                pb0 = *(const float4*)Bp;
                pb1 = *(const float4*)(Bp + 64);
            }
        }

        #pragma unroll
        for (int k = 0; k < 16; k++){
            float4 a0 = *(float4*)&As[k][ty*8];
            float4 a1 = *(float4*)&As[k][ty*8 + 4];
            float4 b0 = *(float4*)&Bs[k][tx*8];
            float4 b1 = *(float4*)&Bs[k][tx*8 + 4];
            float ar[8] = {a0.x,a0.y,a0.z,a0.w,a1.x,a1.y,a1.z,a1.w};
            float bc[8] = {b0.x,b0.y,b0.z,b0.w,b1.x,b1.y,b1.z,b1.w};
            #pragma unroll
            for (int i = 0; i < 8; i++)
                #pragma unroll
                for (int j = 0; j < 8; j++)
                    acc[i][j] += ar[i] * bc[j];
        }
        __syncthreads();
    }

    // epilogue
    if (mode <= 3){
        #pragma unroll
        for (int i = 0; i < 8; i++){
            int m = bm + ty*8 + i;
            float* Crow = C + (size_t)m * Ndim;
            #pragma unroll
            for (int jj = 0; jj < 8; jj += 4){
                int n = bn + tx*8 + jj;
                float4 v = make_float4(acc[i][jj], acc[i][jj+1], acc[i][jj+2], acc[i][jj+3]);
                if (mode == 1){
                    float4 r = *(const float4*)&resid[(size_t)m * Ndim + n];
                    v.x += r.x; v.y += r.y; v.z += r.z; v.w += r.w;
                } else if (mode == 2){
                    float4 bb = *(const float4*)&bias[n];
                    v.x = gelu_exact(v.x + bb.x); v.y = gelu_exact(v.y + bb.y);
                    v.z = gelu_exact(v.z + bb.z); v.w = gelu_exact(v.w + bb.w);
                } else if (mode == 3){
                    float4 bb = *(const float4*)&bias[n];
                    float4 r  = *(const float4*)&resid[(size_t)m * Ndim + n];
                    v.x += bb.x + r.x; v.y += bb.y + r.y;
                    v.z += bb.z + r.z; v.w += bb.w + r.w;
                }
                *(float4*)&Crow[n] = v;
            }
        }
    } else {
        #pragma unroll
        for (int i = 0; i < 8; i++){
            int m = bm + ty*8 + i;
            int b = m >> 11, s = m & 2047;
            #pragma unroll
            for (int j = 0; j < 8; j++){
                int n = bn + tx*8 + j;
                int h = n >> 6, e = n & 63;
                if (mode == 4){
                    C[(((size_t)b*HQ + h)*SQ + s)*DHQ + e] = acc[i][j];
                } else {
                    int flat = s*DHQ + e;     // raw-reshape quirk
                    C[(((size_t)b*HQ + h)*DHQ + (flat >> 11))*SQ + (flat & 2047)] = acc[i][j];
                }
            }
        }
    }
}

// ---------------- fused attention: flash-style, 64x64 tiles, fp32 ----------------
// scores[b,h,s,t] = (1/D) * sum_e Q[b,h,s,e] * Kr[b,h,e,t]; softmax over t; @V.
// Output written directly in concat layout hc[b, s, h*64+e].
__global__ __launch_bounds__(256) void attn_kernel(const float* __restrict__ Q,
                                                   const float* __restrict__ Kr,
                                                   const float* __restrict__ V,
                                                   float* __restrict__ hc)
{
    __shared__ float Qs[64][64];
    __shared__ float SP[64][64];   // K-block, then reused for P
    __shared__ float Vs[64][64];

    int bh = blockIdx.y;
    int b = bh >> 4, h = bh & 15;
    int m0 = blockIdx.x << 6;
    const float* Qbh = Q  + (size_t)bh * SQ * DHQ;
    const float* Kbh = Kr + (size_t)bh * DHQ * SQ;
    const float* Vbh = V  + (size_t)bh * SQ * DHQ;
    int tid = threadIdx.x, ty = tid >> 4, tx = tid & 15;

    // load Q tile once
    for (int i = tid; i < 64*16; i += 256){
        int r = i >> 4, c4 = i & 15;
        *(float4*)&Qs[r][c4*4] = *(const float4*)&Qbh[(size_t)(m0 + r) * DHQ + c4*4];
    }

    float acc[4][4];
    float mi[4], li[4];
    #pragma unroll
    for (int i = 0; i < 4; i++){
        mi[i] = -1e30f; li[i] = 0.f;
        #pragma unroll
        for (int j = 0; j < 4; j++) acc[i][j] = 0.f;
    }
    const float scale = 1.0f / 1024.0f;   // quirk: 1/d_model

    for (int n0 = 0; n0 < SQ; n0 += 64){
        for (int i = tid; i < 64*16; i += 256){
            int e = i >> 4, t4 = i & 15;
            *(float4*)&SP[e][t4*4] = *(const float4*)&Kbh[(size_t)e * SQ + n0 + t4*4];
        }
        for (int i = tid; i < 64*16; i += 256){
            int r = i >> 4, c4 = i & 15;
            *(float4*)&Vs[r][c4*4] = *(const float4*)&Vbh[(size_t)(n0 + r) * DHQ + c4*4];
        }
        __syncthreads();

        // GEMM1: sc = Q @ K_block
        float sc[4][4];
        #pragma unroll
        for (int i = 0; i < 4; i++)
            #pragma unroll
            for (int j = 0; j < 4; j++) sc[i][j] = 0.f;
        #pragma unroll 16
        for (int k = 0; k < 64; k++){
            float a0 = Qs[ty*4+0][k], a1 = Qs[ty*4+1][k];
            float a2 = Qs[ty*4+2][k], a3 = Qs[ty*4+3][k];
            float4 bv = *(float4*)&SP[k][tx*4];
            sc[0][0] += a0*bv.x; sc[0][1] += a0*bv.y; sc[0][2] += a0*bv.z; sc[0][3] += a0*bv.w;
            sc[1][0] += a1*bv.x; sc[1][1] += a1*bv.y; sc[1][2] += a1*bv.z; sc[1][3] += a1*bv.w;
            sc[2][0] += a2*bv.x; sc[2][1] += a2*bv.y; sc[2][2] += a2*bv.z; sc[2][3] += a2*bv.w;
            sc[3][0] += a3*bv.x; sc[3][1] += a3*bv.y; sc[3][2] += a3*bv.z; sc[3][3] += a3*bv.w;
        }

        // online softmax (rows shared by 16 lanes: shfl_xor within 16-lane groups)
        #pragma unroll
        for (int i = 0; i < 4; i++){
            float mx = -1e30f;
            #pragma unroll
            for (int j = 0; j < 4; j++){ sc[i][j] *= scale; mx = fmaxf(mx, sc[i][j]); }
            #pragma unroll
            for (int off = 1; off < 16; off <<= 1)
                mx = fmaxf(mx, __shfl_xor_sync(0xffffffffu, mx, off));
            float mnew  = fmaxf(mi[i], mx);
            float alpha = __expf(mi[i] - mnew);
            mi[i] = mnew;
            float ps = 0.f;
            #pragma unroll
            for (int j = 0; j < 4; j++){
                float p = __expf(sc[i][j] - mnew);
                sc[i][j] = p; ps += p;
            }
            #pragma unroll
            for (int off = 1; off < 16; off <<= 1)
                ps += __shfl_xor_sync(0xffffffffu, ps, off);
            li[i] = li[i] * alpha + ps;
            #pragma unroll
            for (int j = 0; j < 4; j++) acc[i][j] *= alpha;
        }

        __syncthreads();   // everyone done reading K-block before overwrite with P
        #pragma unroll
        for (int i = 0; i < 4; i++)
            #pragma unroll
            for (int j = 0; j < 4; j++)
                SP[ty*4+i][tx*4+j] = sc[i][j];
        __syncthreads();

        // GEMM2: acc += P @ V_block
        #pragma unroll 16
        for (int n = 0; n < 64; n++){
            float a0 = SP[ty*4+0][n], a1 = SP[ty*4+1][n];
            float a2 = SP[ty*4+2][n], a3 = SP[ty*4+3][n];
            float4 bv = *(float4*)&Vs[n][tx*4];
            acc[0][0] += a0*bv.x; acc[0][1] += a0*bv.y; acc[0][2] += a0*bv.z; acc[0][3] += a0*bv.w;
            acc[1][0] += a1*bv.x; acc[1][1] += a1*bv.y; acc[1][2] += a1*bv.z; acc[1][3] += a1*bv.w;
            acc[2][0] += a2*bv.x; acc[2][1] += a2*bv.y; acc[2][2] += a2*bv.z; acc[2][3] += a2*bv.w;
            acc[3][0] += a3*bv.x; acc[3][1] += a3*bv.y; acc[3][2] += a3*bv.z; acc[3][3] += a3*bv.w;
        }
        __syncthreads();
    }

    // write heads in concat layout [B, S, H*DH]
    #pragma unroll
    for (int i = 0; i < 4; i++){
        int row = m0 + ty*4 + i;
        float invl = 1.0f / li[i];
        float4 o = make_float4(acc[i][0]*invl, acc[i][1]*invl, acc[i][2]*invl, acc[i][3]*invl);
        *(float4*)&hc[((size_t)b*SQ + row)*DQ + h*64 + tx*4] = o;
    }
}

// ---------------- launch ----------------
extern "C" void kernel_launch(void* const* d_in, const int* in_sizes, int n_in,
                              void* d_out, int out_size)
{
    const float* x      = (const float*)d_in[0];
    const float* W_Q    = (const float*)d_in[1];
    const float* W_K    = (const float*)d_in[2];
    const float* W_V    = (const float*)d_in[3];
    const float* W_O    = (const float*)d_in[4];
    const float* W_up   = (const float*)d_in[5];
    const float* b_up   = (const float*)d_in[6];
    const float* W_down = (const float*)d_in[7];
    const float* b_down = (const float*)d_in[8];
    const float* gamma1 = (const float*)d_in[9];
    const float* beta1  = (const float*)d_in[10];
    const float* gamma2 = (const float*)d_in[11];
    const float* beta2  = (const float*)d_in[12];
    float* out = (float*)d_out;

    float *u, *Qp, *Krp, *Vp, *hcp, *z1, *v1, *v3;
    cudaGetSymbolAddress((void**)&u,   g_u);
    cudaGetSymbolAddress((void**)&Qp,  g_Q);
    cudaGetSymbolAddress((void**)&Krp, g_Kr);
    cudaGetSymbolAddress((void**)&Vp,  g_V);
    cudaGetSymbolAddress((void**)&hcp, g_hc);
    cudaGetSymbolAddress((void**)&z1,  g_z1);
    cudaGetSymbolAddress((void**)&v1,  g_v1);
    cudaGetSymbolAddress((void**)&v3,  g_v3);

    // 1. LN1
    ln_kernel<<<MQ, 256>>>(x, gamma1, beta1, u);
    // 2. QKV projections (B transposed), scatter epilogues
    sgemm_kernel<<<dim3(DQ/128, MQ/128), 256>>>(u, W_Q, Qp,  MQ, DQ, DQ, 1, 4, nullptr, nullptr);
    sgemm_kernel<<<dim3(DQ/128, MQ/128), 256>>>(u, W_K, Krp, MQ, DQ, DQ, 1, 5, nullptr, nullptr);
    sgemm_kernel<<<dim3(DQ/128, MQ/128), 256>>>(u, W_V, Vp,  MQ, DQ, DQ, 1, 4, nullptr, nullptr);
    // 3. fused attention
    attn_kernel<<<dim3(SQ/64, BQ*HQ), 256>>>(Qp, Krp, Vp, hcp);
    // 4. O projection + residual x
    sgemm_kernel<<<dim3(DQ/128, MQ/128), 256>>>(hcp, W_O, z1, MQ, DQ, DQ, 0, 1, nullptr, x);
    // 5. LN2
    ln_kernel<<<MQ, 256>>>(z1, gamma2, beta2, v1);
    // 6. FFN up + bias + exact GELU
    sgemm_kernel<<<dim3(FQ/128, MQ/128), 256>>>(v1, W_up, v3, MQ, FQ, DQ, 0, 2, b_up, nullptr);
    // 7. FFN down + bias + residual z1 -> out
    sgemm_kernel<<<dim3(DQ/128, MQ/128), 256>>>(v3, W_down, out, MQ, DQ, FQ, 0, 3, b_down, z1);
}

// round 3
// speedup vs baseline: 1.9345x; 1.9345x over previous
#include <cuda_runtime.h>
#include <math.h>
#include <stdint.h>

#define BQ 2
#define SQ 2048
#define DQ 1024
#define HQ 16
#define DHQ 64
#define FQ 4096
#define MQ (BQ*SQ)   // 4096 rows

// ---------------- scratch (device globals; no allocation allowed) ----------------
__device__ float g_u [MQ*DQ];
__device__ float g_Q [BQ*HQ*SQ*DHQ];
__device__ float g_Kr[BQ*HQ*DHQ*SQ];
__device__ float g_V [BQ*HQ*SQ*DHQ];
__device__ float g_hc[MQ*DQ];
__device__ float g_z1[MQ*DQ];
__device__ float g_v1[MQ*DQ];
__device__ float g_v3[MQ*FQ];
__device__ float g_WOt [DQ*DQ];    // W_O^T  : [D, H*DH]
__device__ float g_Wupt[FQ*DQ];    // W_up^T : [F, D]
__device__ float g_Wdnt[DQ*FQ];    // W_down^T : [D, F]

__device__ __forceinline__ uint32_t f2tf32(float x){
    uint32_t r;
    asm("cvt.rna.tf32.f32 %0, %1;" : "=r"(r) : "f"(x));
    return r;
}
__device__ __forceinline__ float gelu_exact(float x){
    return 0.5f * x * (1.0f + erff(x * 0.70710678118654752f));
}

// m16n8k8 tf32 mma, fp32 accumulate (baseline PTX ISA, works on compute_103)
__device__ __forceinline__ void mma_tf32(float* c, const uint32_t* a, const uint32_t* b){
    asm volatile("mma.sync.aligned.m16n8k8.row.col.f32.tf32.tf32.f32 "
        "{%0,%1,%2,%3}, {%4,%5,%6,%7}, {%8,%9}, {%0,%1,%2,%3};"
        : "+f"(c[0]), "+f"(c[1]), "+f"(c[2]), "+f"(c[3])
        : "r"(a[0]), "r"(a[1]), "r"(a[2]), "r"(a[3]), "r"(b[0]), "r"(b[1]));
}

// ---------------- LayerNorm ----------------
__global__ __launch_bounds__(256) void ln_kernel(const float* __restrict__ x,
                                                 const float* __restrict__ gamma,
                                                 const float* __restrict__ beta,
                                                 float* __restrict__ out)
{
    int row = blockIdx.x;
    int t = threadIdx.x;
    const float4* xr = (const float4*)(x + (size_t)row * DQ);
    float4 v = xr[t];
    float s  = v.x + v.y + v.z + v.w;
    float s2 = v.x*v.x + v.y*v.y + v.z*v.z + v.w*v.w;
    #pragma unroll
    for (int off = 16; off; off >>= 1){
        s  += __shfl_xor_sync(0xffffffffu, s,  off);
        s2 += __shfl_xor_sync(0xffffffffu, s2, off);
    }
    __shared__ float sm[8], sm2[8];
    int w = t >> 5, lane = t & 31;
    if (!lane){ sm[w] = s; sm2[w] = s2; }
    __syncthreads();
    if (t == 0){
        float a = 0.f, b = 0.f;
        #pragma unroll
        for (int i = 0; i < 8; i++){ a += sm[i]; b += sm2[i]; }
        sm[0] = a; sm2[0] = b;
    }
    __syncthreads();
    float mu  = sm[0]  * (1.0f / DQ);
    float var = sm2[0] * (1.0f / DQ) - mu * mu;
    float inv = rsqrtf(var + 1e-5f);
    float4 g  = ((const float4*)gamma)[t];
    float4 be = ((const float4*)beta)[t];
    float4 o;
    o.x = (v.x - mu) * inv * g.x + be.x;
    o.y = (v.y - mu) * inv * g.y + be.y;
    o.z = (v.z - mu) * inv * g.z + be.z;
    o.w = (v.w - mu) * inv * g.w + be.w;
    ((float4*)(out + (size_t)row * DQ))[t] = o;
}

// ---------------- transpose: out[C,R] = in[R,C]^T ----------------
__global__ __launch_bounds__(256) void transpose_kernel(const float* __restrict__ in,
                                                        float* __restrict__ out,
                                                        int R, int Ccols)
{
    __shared__ float t[32][33];
    int c0 = blockIdx.x * 32, r0 = blockIdx.y * 32;
    int x = threadIdx.x, y = threadIdx.y;   // 32x8
    #pragma unroll
    for (int i = 0; i < 32; i += 8)
        t[y + i][x] = in[(size_t)(r0 + y + i) * Ccols + c0 + x];
    __syncthreads();
    #pragma unroll
    for (int i = 0; i < 32; i += 8)
        out[(size_t)(c0 + y + i) * R + r0 + x] = t[x][y + i];
}

// ---------------- mma.sync tf32 GEMM: C = A[M,K] @ Bt[N,K]^T, 128x128 tile ----------------
// MODE: 0 plain | 1 +resid | 2 gelu(acc+bias) | 3 acc+bias+resid
//       4 scatter [B,H,S,DH] | 5 scatter quirky K_r [B,H,DH,S]
template<int MODE>
__global__ __launch_bounds__(256, 2) void mma_gemm(
    const float* __restrict__ A, const float* __restrict__ Bt,
    float* __restrict__ C, int Mdim, int Ndim, int Kdim,
    const float* __restrict__ bias, const float* __restrict__ resid)
{
    __shared__ float As[128][20];   // [m][k], pad 20 -> conflict-free frag loads
    __shared__ float Bs[128][20];   // [n][k]

    int tid = threadIdx.x, wid = tid >> 5, lane = tid & 31;
    int grp = lane >> 2, tig = lane & 3;
    int wm0 = (wid & 3) << 5;       // warp rows: 32
    int wn0 = (wid >> 2) << 6;      // warp cols: 64
    int bm = blockIdx.y << 7, bn = blockIdx.x << 7;

    float acc[2][8][4];
    #pragma unroll
    for (int mt = 0; mt < 2; mt++)
        #pragma unroll
        for (int nt = 0; nt < 8; nt++)
            #pragma unroll
            for (int q = 0; q < 4; q++) acc[mt][nt][q] = 0.f;

    int r0 = tid >> 2;             // 0..63
    int c4 = (tid & 3) * 4;        // 0,4,8,12

    // prefetch chunk 0
    float4 pa0 = *(const float4*)&A [(size_t)(bm + r0)      * Kdim + c4];
    float4 pa1 = *(const float4*)&A [(size_t)(bm + r0 + 64) * Kdim + c4];
    float4 pb0 = *(const float4*)&Bt[(size_t)(bn + r0)      * Kdim + c4];
    float4 pb1 = *(const float4*)&Bt[(size_t)(bn + r0 + 64) * Kdim + c4];

    int nc = Kdim >> 4;
    for (int ch = 0; ch < nc; ch++){
        // commit regs -> smem (tf32-rounded)
        As[r0][c4+0]      = __uint_as_float(f2tf32(pa0.x));
        As[r0][c4+1]      = __uint_as_float(f2tf32(pa0.y));
        As[r0][c4+2]      = __uint_as_float(f2tf32(pa0.z));
        As[r0][c4+3]      = __uint_as_float(f2tf32(pa0.w));
        As[r0+64][c4+0]   = __uint_as_float(f2tf32(pa1.x));
        As[r0+64][c4+1]   = __uint_as_float(f2tf32(pa1.y));
        As[r0+64][c4+2]   = __uint_as_float(f2tf32(pa1.z));
        As[r0+64][c4+3]   = __uint_as_float(f2tf32(pa1.w));
        Bs[r0][c4+0]      = __uint_as_float(f2tf32(pb0.x));
        Bs[r0][c4+1]      = __uint_as_float(f2tf32(pb0.y));
        Bs[r0][c4+2]      = __uint_as_float(f2tf32(pb0.z));
        Bs[r0][c4+3]      = __uint_as_float(f2tf32(pb0.w));
        Bs[r0+64][c4+0]   = __uint_as_float(f2tf32(pb1.x));
        Bs[r0+64][c4+1]   = __uint_as_float(f2tf32(pb1.y));
        Bs[r0+64][c4+2]   = __uint_as_float(f2tf32(pb1.z));
        Bs[r0+64][c4+3]   = __uint_as_float(f2tf32(pb1.w));
        __syncthreads();

        // prefetch next chunk while computing this one
        if (ch + 1 < nc){
            int kg = ((ch + 1) << 4) + c4;
            pa0 = *(const float4*)&A [(size_t)(bm + r0)      * Kdim + kg];
            pa1 = *(const float4*)&A [(size_t)(bm + r0 + 64) * Kdim + kg];
            pb0 = *(const float4*)&Bt[(size_t)(bn + r0)      * Kdim + kg];
            pb1 = *(const float4*)&Bt[(size_t)(bn + r0 + 64) * Kdim + kg];
        }

        #pragma unroll
        for (int ks = 0; ks < 2; ks++){
            int kk = ks << 3;
            uint32_t af[2][4], bf[8][2];
            #pragma unroll
            for (int mt = 0; mt < 2; mt++){
                int mr = wm0 + mt*16 + grp;
                af[mt][0] = __float_as_uint(As[mr  ][kk + tig]);
                af[mt][1] = __float_as_uint(As[mr+8][kk + tig]);
                af[mt][2] = __float_as_uint(As[mr  ][kk + tig + 4]);
                af[mt][3] = __float_as_uint(As[mr+8][kk + tig + 4]);
            }
            #pragma unroll
            for (int nt = 0; nt < 8; nt++){
                int nr = wn0 + nt*8 + grp;
                bf[nt][0] = __float_as_uint(Bs[nr][kk + tig]);
                bf[nt][1] = __float_as_uint(Bs[nr][kk + tig + 4]);
            }
            #pragma unroll
            for (int mt = 0; mt < 2; mt++)
                #pragma unroll
                for (int nt = 0; nt < 8; nt++)
                    mma_tf32(acc[mt][nt], af[mt], bf[nt]);
        }
        __syncthreads();
    }

    // -------- epilogue --------
    #pragma unroll
    for (int mt = 0; mt < 2; mt++){
        #pragma unroll
        for (int half = 0; half < 2; half++){          // c0c1 (row) vs c2c3 (row+8)
            int m = bm + wm0 + mt*16 + grp + half*8;
            #pragma unroll
            for (int nt = 0; nt < 8; nt++){
                int n = bn + wn0 + nt*8 + tig*2;
                float v0 = acc[mt][nt][half*2 + 0];
                float v1 = acc[mt][nt][half*2 + 1];
                if (MODE <= 3){
                    if (MODE == 1){
                        float2 r = *(const float2*)&resid[(size_t)m * Ndim + n];
                        v0 += r.x; v1 += r.y;
                    } else if (MODE == 2){
                        float2 bb = *(const float2*)&bias[n];
                        v0 = gelu_exact(v0 + bb.x); v1 = gelu_exact(v1 + bb.y);
                    } else if (MODE == 3){
                        float2 bb = *(const float2*)&bias[n];
                        float2 r  = *(const float2*)&resid[(size_t)m * Ndim + n];
                        v0 += bb.x + r.x; v1 += bb.y + r.y;
                    }
                    *(float2*)&C[(size_t)m * Ndim + n] = make_float2(v0, v1);
                } else {
                    int b = m >> 11, s = m & 2047;
                    int h = n >> 6, e = n & 63;
                    if (MODE == 4){
                        *(float2*)&C[(((size_t)b*HQ + h)*SQ + s)*DHQ + e] = make_float2(v0, v1);
                    } else {
                        int flat = s * DHQ + e;   // raw-reshape quirk
                        *(float2*)&C[(((size_t)b*HQ + h)*DHQ + (flat >> 11))*SQ + (flat & 2047)]
                            = make_float2(v0, v1);
                    }
                }
            }
        }
    }
}

// ---------------- fused attention (unchanged) ----------------
__global__ __launch_bounds__(256) void attn_kernel(const float* __restrict__ Q,
                                                   const float* __restrict__ Kr,
                                                   const float* __restrict__ V,
                                                   float* __restrict__ hc)
{
    __shared__ float Qs[64][64];
    __shared__ float SP[64][64];
    __shared__ float Vs[64][64];

    int bh = blockIdx.y;
    int b = bh >> 4, h = bh & 15;
    int m0 = blockIdx.x << 6;
    const float* Qbh = Q  + (size_t)bh * SQ * DHQ;
    const float* Kbh = Kr + (size_t)bh * DHQ * SQ;
    const float* Vbh = V  + (size_t)bh * SQ * DHQ;
    int tid = threadIdx.x, ty = tid >> 4, tx = tid & 15;

    for (int i = tid; i < 64*16; i += 256){
        int r = i >> 4, c4 = i & 15;
        *(float4*)&Qs[r][c4*4] = *(const float4*)&Qbh[(size_t)(m0 + r) * DHQ + c4*4];
    }

    float acc[4][4];
    float mi[4], li[4];
    #pragma unroll
    for (int i = 0; i < 4; i++){
        mi[i] = -1e30f; li[i] = 0.f;
        #pragma unroll
        for (int j = 0; j < 4; j++) acc[i][j] = 0.f;
    }
    const float scale = 1.0f / 1024.0f;

    for (int n0 = 0; n0 < SQ; n0 += 64){
        for (int i = tid; i < 64*16; i += 256){
            int e = i >> 4, t4 = i & 15;
            *(float4*)&SP[e][t4*4] = *(const float4*)&Kbh[(size_t)e * SQ + n0 + t4*4];
        }
        for (int i = tid; i < 64*16; i += 256){
            int r = i >> 4, c4 = i & 15;
            *(float4*)&Vs[r][c4*4] = *(const float4*)&Vbh[(size_t)(n0 + r) * DHQ + c4*4];
        }
        __syncthreads();

        float sc[4][4];
        #pragma unroll
        for (int i = 0; i < 4; i++)
            #pragma unroll
            for (int j = 0; j < 4; j++) sc[i][j] = 0.f;
        #pragma unroll 16
        for (int k = 0; k < 64; k++){
            float a0 = Qs[ty*4+0][k], a1 = Qs[ty*4+1][k];
            float a2 = Qs[ty*4+2][k], a3 = Qs[ty*4+3][k];
            float4 bv = *(float4*)&SP[k][tx*4];
            sc[0][0] += a0*bv.x; sc[0][1] += a0*bv.y; sc[0][2] += a0*bv.z; sc[0][3] += a0*bv.w;
            sc[1][0] += a1*bv.x; sc[1][1] += a1*bv.y; sc[1][2] += a1*bv.z; sc[1][3] += a1*bv.w;
            sc[2][0] += a2*bv.x; sc[2][1] += a2*bv.y; sc[2][2] += a2*bv.z; sc[2][3] += a2*bv.w;
            sc[3][0] += a3*bv.x; sc[3][1] += a3*bv.y; sc[3][2] += a3*bv.z; sc[3][3] += a3*bv.w;
        }

        #pragma unroll
        for (int i = 0; i < 4; i++){
            float mx = -1e30f;
            #pragma unroll
            for (int j = 0; j < 4; j++){ sc[i][j] *= scale; mx = fmaxf(mx, sc[i][j]); }
            #pragma unroll
            for (int off = 1; off < 16; off <<= 1)
                mx = fmaxf(mx, __shfl_xor_sync(0xffffffffu, mx, off));
            float mnew  = fmaxf(mi[i], mx);
            float alpha = __expf(mi[i] - mnew);
            mi[i] = mnew;
            float ps = 0.f;
            #pragma unroll
            for (int j = 0; j < 4; j++){
                float p = __expf(sc[i][j] - mnew);
                sc[i][j] = p; ps += p;
            }
            #pragma unroll
            for (int off = 1; off < 16; off <<= 1)
                ps += __shfl_xor_sync(0xffffffffu, ps, off);
            li[i] = li[i] * alpha + ps;
            #pragma unroll
            for (int j = 0; j < 4; j++) acc[i][j] *= alpha;
        }

        __syncthreads();
        #pragma unroll
        for (int i = 0; i < 4; i++)
            #pragma unroll
            for (int j = 0; j < 4; j++)
                SP[ty*4+i][tx*4+j] = sc[i][j];
        __syncthreads();

        #pragma unroll 16
        for (int n = 0; n < 64; n++){
            float a0 = SP[ty*4+0][n], a1 = SP[ty*4+1][n];
            float a2 = SP[ty*4+2][n], a3 = SP[ty*4+3][n];
            float4 bv = *(float4*)&Vs[n][tx*4];
            acc[0][0] += a0*bv.x; acc[0][1] += a0*bv.y; acc[0][2] += a0*bv.z; acc[0][3] += a0*bv.w;
            acc[1][0] += a1*bv.x; acc[1][1] += a1*bv.y; acc[1][2] += a1*bv.z; acc[1][3] += a1*bv.w;
            acc[2][0] += a2*bv.x; acc[2][1] += a2*bv.y; acc[2][2] += a2*bv.z; acc[2][3] += a2*bv.w;
            acc[3][0] += a3*bv.x; acc[3][1] += a3*bv.y; acc[3][2] += a3*bv.z; acc[3][3] += a3*bv.w;
        }
        __syncthreads();
    }

    #pragma unroll
    for (int i = 0; i < 4; i++){
        int row = m0 + ty*4 + i;
        float invl = 1.0f / li[i];
        float4 o = make_float4(acc[i][0]*invl, acc[i][1]*invl, acc[i][2]*invl, acc[i][3]*invl);
        *(float4*)&hc[((size_t)b*SQ + row)*DQ + h*64 + tx*4] = o;
    }
}

// ---------------- launch ----------------
extern "C" void kernel_launch(void* const* d_in, const int* in_sizes, int n_in,
                              void* d_out, int out_size)
{
    const float* x      = (const float*)d_in[0];
    const float* W_Q    = (const float*)d_in[1];
    const float* W_K    = (const float*)d_in[2];
    const float* W_V    = (const float*)d_in[3];
    const float* W_O    = (const float*)d_in[4];
    const float* W_up   = (const float*)d_in[5];
    const float* b_up   = (const float*)d_in[6];
    const float* W_down = (const float*)d_in[7];
    const float* b_down = (const float*)d_in[8];
    const float* gamma1 = (const float*)d_in[9];
    const float* beta1  = (const float*)d_in[10];
    const float* gamma2 = (const float*)d_in[11];
    const float* beta2  = (const float*)d_in[12];
    float* out = (float*)d_out;

    float *u, *Qp, *Krp, *Vp, *hcp, *z1, *v1, *v3, *WOt, *Wupt, *Wdnt;
    cudaGetSymbolAddress((void**)&u,    g_u);
    cudaGetSymbolAddress((void**)&Qp,   g_Q);
    cudaGetSymbolAddress((void**)&Krp,  g_Kr);
    cudaGetSymbolAddress((void**)&Vp,   g_V);
    cudaGetSymbolAddress((void**)&hcp,  g_hc);
    cudaGetSymbolAddress((void**)&z1,   g_z1);
    cudaGetSymbolAddress((void**)&v1,   g_v1);
    cudaGetSymbolAddress((void**)&v3,   g_v3);
    cudaGetSymbolAddress((void**)&WOt,  g_WOt);
    cudaGetSymbolAddress((void**)&Wupt, g_Wupt);
    cudaGetSymbolAddress((void**)&Wdnt, g_Wdnt);

    // weight transposes (NN -> NT)
    transpose_kernel<<<dim3(DQ/32, DQ/32), dim3(32,8)>>>(W_O,    WOt,  DQ, DQ);
    transpose_kernel<<<dim3(FQ/32, DQ/32), dim3(32,8)>>>(W_up,   Wupt, DQ, FQ);
    transpose_kernel<<<dim3(DQ/32, FQ/32), dim3(32,8)>>>(W_down, Wdnt, FQ, DQ);

    // 1. LN1
    ln_kernel<<<MQ, 256>>>(x, gamma1, beta1, u);
    // 2. QKV projections (tensor-core tf32), scatter epilogues
    mma_gemm<4><<<dim3(DQ/128, MQ/128), 256>>>(u, W_Q, Qp,  MQ, DQ, DQ, nullptr, nullptr);
    mma_gemm<5><<<dim3(DQ/128, MQ/128), 256>>>(u, W_K, Krp, MQ, DQ, DQ, nullptr, nullptr);
    mma_gemm<4><<<dim3(DQ/128, MQ/128), 256>>>(u, W_V, Vp,  MQ, DQ, DQ, nullptr, nullptr);
    // 3. fused attention
    attn_kernel<<<dim3(SQ/64, BQ*HQ), 256>>>(Qp, Krp, Vp, hcp);
    // 4. O projection + residual x
    mma_gemm<1><<<dim3(DQ/128, MQ/128), 256>>>(hcp, WOt, z1, MQ, DQ, DQ, nullptr, x);
    // 5. LN2
    ln_kernel<<<MQ, 256>>>(z1, gamma2, beta2, v1);
    // 6. FFN up + bias + exact GELU
    mma_gemm<2><<<dim3(FQ/128, MQ/128), 256>>>(v1, Wupt, v3, MQ, FQ, DQ, b_up, nullptr);
    // 7. FFN down + bias + residual z1 -> out
    mma_gemm<3><<<dim3(DQ/128, MQ/128), 256>>>(v3, Wdnt, out, MQ, DQ, FQ, b_down, z1);
}

// round 4
// speedup vs baseline: 2.5107x; 1.2979x over previous
#include <cuda_runtime.h>
#include <math.h>
#include <stdint.h>

#define BQ 2
#define SQ 2048
#define DQ 1024
#define HQ 16
#define DHQ 64
#define FQ 4096
#define MQ (BQ*SQ)   // 4096 rows

// ---------------- scratch (device globals; no allocation allowed) ----------------
__device__ float g_u  [MQ*DQ];
__device__ float g_Q  [BQ*HQ*SQ*DHQ];
__device__ float g_Kr [BQ*HQ*DHQ*SQ];
__device__ float g_V  [BQ*HQ*SQ*DHQ];
__device__ float g_hc [MQ*DQ];
__device__ float g_z1 [MQ*DQ];
__device__ float g_v1 [MQ*DQ];
__device__ float g_v3 [MQ*FQ];
__device__ float g_WOt [DQ*DQ];
__device__ float g_Wupt[FQ*DQ];
__device__ float g_Wdnt[DQ*FQ];
__device__ float g_WQr [DQ*DQ];
__device__ float g_WKr [DQ*DQ];
__device__ float g_WVr [DQ*DQ];

// ---------------- helpers ----------------
__device__ __forceinline__ uint32_t smem_u32(const void* p){
    uint32_t a;
    asm("{ .reg .u64 t; cvta.to.shared.u64 t, %1; cvt.u32.u64 %0, t; }" : "=r"(a) : "l"(p));
    return a;
}
__device__ __forceinline__ float rnd_tf32(float x){
    uint32_t r;
    asm("cvt.rna.tf32.f32 %0, %1;" : "=r"(r) : "f"(x));
    return __uint_as_float(r);
}
__device__ __forceinline__ float gelu_exact(float x){
    return 0.5f * x * (1.0f + erff(x * 0.70710678118654752f));
}
__device__ __forceinline__ void mma_tf32(float* c, const uint32_t* a, const uint32_t* b){
    asm volatile("mma.sync.aligned.m16n8k8.row.col.f32.tf32.tf32.f32 "
        "{%0,%1,%2,%3}, {%4,%5,%6,%7}, {%8,%9}, {%0,%1,%2,%3};"
        : "+f"(c[0]), "+f"(c[1]), "+f"(c[2]), "+f"(c[3])
        : "r"(a[0]), "r"(a[1]), "r"(a[2]), "r"(a[3]), "r"(b[0]), "r"(b[1]));
}
#define CP16(d, s)  asm volatile("cp.async.cg.shared.global [%0], [%1], 16;" :: "r"(d), "l"(s) : "memory")
#define CP_COMMIT   asm volatile("cp.async.commit_group;" ::: "memory")
#define CP_WAIT0    asm volatile("cp.async.wait_group 0;" ::: "memory")
#define CP_WAIT1    asm volatile("cp.async.wait_group 1;" ::: "memory")

// ---------------- LayerNorm (optionally tf32-rounded output) ----------------
template<int ROUND>
__global__ __launch_bounds__(256) void ln_kernel(const float* __restrict__ x,
                                                 const float* __restrict__ gamma,
                                                 const float* __restrict__ beta,
                                                 float* __restrict__ out)
{
    int row = blockIdx.x;
    int t = threadIdx.x;
    const float4* xr = (const float4*)(x + (size_t)row * DQ);
    float4 v = xr[t];
    float s  = v.x + v.y + v.z + v.w;
    float s2 = v.x*v.x + v.y*v.y + v.z*v.z + v.w*v.w;
    #pragma unroll
    for (int off = 16; off; off >>= 1){
        s  += __shfl_xor_sync(0xffffffffu, s,  off);
        s2 += __shfl_xor_sync(0xffffffffu, s2, off);
    }
    __shared__ float sm[8], sm2[8];
    int w = t >> 5, lane = t & 31;
    if (!lane){ sm[w] = s; sm2[w] = s2; }
    __syncthreads();
    if (t == 0){
        float a = 0.f, b = 0.f;
        #pragma unroll
        for (int i = 0; i < 8; i++){ a += sm[i]; b += sm2[i]; }
        sm[0] = a; sm2[0] = b;
    }
    __syncthreads();
    float mu  = sm[0]  * (1.0f / DQ);
    float var = sm2[0] * (1.0f / DQ) - mu * mu;
    float inv = rsqrtf(var + 1e-5f);
    float4 g  = ((const float4*)gamma)[t];
    float4 be = ((const float4*)beta)[t];
    float4 o;
    o.x = (v.x - mu) * inv * g.x + be.x;
    o.y = (v.y - mu) * inv * g.y + be.y;
    o.z = (v.z - mu) * inv * g.z + be.z;
    o.w = (v.w - mu) * inv * g.w + be.w;
    if (ROUND){
        o.x = rnd_tf32(o.x); o.y = rnd_tf32(o.y);
        o.z = rnd_tf32(o.z); o.w = rnd_tf32(o.w);
    }
    ((float4*)(out + (size_t)row * DQ))[t] = o;
}

// ---------------- transpose + tf32 round: out[C,R] = round(in[R,C]^T) ----------------
__global__ __launch_bounds__(256) void transpose_kernel(const float* __restrict__ in,
                                                        float* __restrict__ out,
                                                        int R, int Ccols)
{
    __shared__ float t[32][33];
    int c0 = blockIdx.x * 32, r0 = blockIdx.y * 32;
    int x = threadIdx.x, y = threadIdx.y;   // 32x8
    #pragma unroll
    for (int i = 0; i < 32; i += 8)
        t[y + i][x] = in[(size_t)(r0 + y + i) * Ccols + c0 + x];
    __syncthreads();
    #pragma unroll
    for (int i = 0; i < 32; i += 8)
        out[(size_t)(c0 + y + i) * R + r0 + x] = rnd_tf32(t[x][y + i]);
}

// ---------------- round copy (weights used untransposed) ----------------
__global__ __launch_bounds__(256) void round_copy_kernel(const float* __restrict__ in,
                                                         float* __restrict__ out, int n4)
{
    int i = blockIdx.x * blockDim.x + threadIdx.x;
    for (; i < n4; i += gridDim.x * blockDim.x){
        float4 v = ((const float4*)in)[i];
        v.x = rnd_tf32(v.x); v.y = rnd_tf32(v.y);
        v.z = rnd_tf32(v.z); v.w = rnd_tf32(v.w);
        ((float4*)out)[i] = v;
    }
}

// ---------------- GEMM v2: C = A[M,K] @ Bt[N,K]^T, CTA 256x128, warp 64x64 ----------------
// Inputs pre-rounded to tf32. cp.async double-buffered.
// MODE: 1 +resid | 2 round(gelu(acc+bias)) | 3 acc+bias+resid
//       4 round->scatter [B,H,S,DH] | 5 round->scatter quirky K_r [B,H,DH,S]
#define ASTRIDE 20
template<int MODE>
__global__ __launch_bounds__(256) void mma_gemm(
    const float* __restrict__ A, const float* __restrict__ Bt,
    float* __restrict__ C, int Mdim, int Ndim, int Kdim,
    const float* __restrict__ bias, const float* __restrict__ resid)
{
    extern __shared__ float sh[];
    float* Abuf[2] = { sh,          sh + 256*ASTRIDE };
    float* Bbuf[2] = { sh + 512*ASTRIDE, sh + 512*ASTRIDE + 128*ASTRIDE };

    int tid = threadIdx.x, wid = tid >> 5, lane = tid & 31;
    int grp = lane >> 2, tig = lane & 3;
    int wm0 = (wid & 3) << 6;    // 0,64,128,192
    int wn0 = (wid >> 2) << 6;   // 0,64
    int bm = blockIdx.y << 8, bn = blockIdx.x << 7;

    uint32_t sA[2] = { smem_u32(Abuf[0]), smem_u32(Abuf[1]) };
    uint32_t sB[2] = { smem_u32(Bbuf[0]), smem_u32(Bbuf[1]) };

    const float* aSrcBase = A  + (size_t)(bm + tid) * Kdim;
    const float* bSrcBase = Bt + (size_t)(bn + (tid >> 1)) * Kdim + (tid & 1) * 8;
    uint32_t aDst = sA[0] + tid * (ASTRIDE*4);                 // per-buffer delta applied below
    uint32_t bDst = sB[0] + (tid >> 1) * (ASTRIDE*4) + (tid & 1) * 32;

    auto load_chunk = [&](int ch){
        int buf = ch & 1;
        int k0 = ch << 4;
        uint32_t da = sA[buf] + tid * (ASTRIDE*4);
        const float* sa = aSrcBase + k0;
        CP16(da,      sa);
        CP16(da + 16, sa + 4);
        CP16(da + 32, sa + 8);
        CP16(da + 48, sa + 12);
        uint32_t db = sB[buf] + (tid >> 1) * (ASTRIDE*4) + (tid & 1) * 32;
        const float* sb = bSrcBase + k0;
        CP16(db,      sb);
        CP16(db + 16, sb + 4);
        CP_COMMIT;
    };
    (void)aDst; (void)bDst;

    int nc = Kdim >> 4;
    load_chunk(0);
    load_chunk(1);

    float acc[4][8][4];
    #pragma unroll
    for (int mt = 0; mt < 4; mt++)
        #pragma unroll
        for (int nt = 0; nt < 8; nt++)
            #pragma unroll
            for (int q = 0; q < 4; q++) acc[mt][nt][q] = 0.f;

    for (int ch = 0; ch < nc; ch++){
        if (ch + 1 < nc) { CP_WAIT1; } else { CP_WAIT0; }
        __syncthreads();
        const float* Sa = Abuf[ch & 1];
        const float* Sb = Bbuf[ch & 1];
        #pragma unroll
        for (int ks = 0; ks < 2; ks++){
            int kk = ks << 3;
            uint32_t af[4][4], bf[8][2];
            #pragma unroll
            for (int mt = 0; mt < 4; mt++){
                int mr = wm0 + mt*16 + grp;
                af[mt][0] = __float_as_uint(Sa[mr*ASTRIDE     + kk + tig]);
                af[mt][1] = __float_as_uint(Sa[(mr+8)*ASTRIDE + kk + tig]);
                af[mt][2] = __float_as_uint(Sa[mr*ASTRIDE     + kk + tig + 4]);
                af[mt][3] = __float_as_uint(Sa[(mr+8)*ASTRIDE + kk + tig + 4]);
            }
            #pragma unroll
            for (int nt = 0; nt < 8; nt++){
                int nr = wn0 + nt*8 + grp;
                bf[nt][0] = __float_as_uint(Sb[nr*ASTRIDE + kk + tig]);
                bf[nt][1] = __float_as_uint(Sb[nr*ASTRIDE + kk + tig + 4]);
            }
            #pragma unroll
            for (int mt = 0; mt < 4; mt++)
                #pragma unroll
                for (int nt = 0; nt < 8; nt++)
                    mma_tf32(acc[mt][nt], af[mt], bf[nt]);
        }
        __syncthreads();
        if (ch + 2 < nc) load_chunk(ch + 2);
    }

    // -------- epilogue --------
    #pragma unroll
    for (int mt = 0; mt < 4; mt++){
        #pragma unroll
        for (int half = 0; half < 2; half++){
            int m = bm + wm0 + mt*16 + grp + half*8;
            #pragma unroll
            for (int nt = 0; nt < 8; nt++){
                int n = bn + wn0 + nt*8 + tig*2;
                float v0 = acc[mt][nt][half*2 + 0];
                float v1 = acc[mt][nt][half*2 + 1];
                if (MODE <= 3){
                    if (MODE == 1){
                        float2 r = *(const float2*)&resid[(size_t)m * Ndim + n];
                        v0 += r.x; v1 += r.y;
                    } else if (MODE == 2){
                        float2 bb = *(const float2*)&bias[n];
                        v0 = rnd_tf32(gelu_exact(v0 + bb.x));
                        v1 = rnd_tf32(gelu_exact(v1 + bb.y));
                    } else if (MODE == 3){
                        float2 bb = *(const float2*)&bias[n];
                        float2 r  = *(const float2*)&resid[(size_t)m * Ndim + n];
                        v0 += bb.x + r.x; v1 += bb.y + r.y;
                    }
                    *(float2*)&C[(size_t)m * Ndim + n] = make_float2(v0, v1);
                } else {
                    v0 = rnd_tf32(v0); v1 = rnd_tf32(v1);
                    int b = m >> 11, s = m & 2047;
                    int h = n >> 6, e = n & 63;
                    if (MODE == 4){
                        *(float2*)&C[(((size_t)b*HQ + h)*SQ + s)*DHQ + e] = make_float2(v0, v1);
                    } else {
                        int flat = s * DHQ + e;   // raw-reshape quirk
                        *(float2*)&C[(((size_t)b*HQ + h)*DHQ + (flat >> 11))*SQ + (flat & 2047)]
                            = make_float2(v0, v1);
                    }
                }
            }
        }
    }
}
static const int GEMM_SMEM = (512*ASTRIDE + 256*ASTRIDE) * 4;  // 61440 B

// ---------------- tensor-core flash attention ----------------
// 4 warps, 64 Q rows per CTA; warp = 16 rows. smem: Qs/Ps stride 68, Ks/Vs stride 72.
#define QST 68
#define KST 72
static const int ATTN_SMEM = (2*64*QST + 2*64*KST) * 4;        // 71680 B

__global__ __launch_bounds__(128) void attn_tc(const float* __restrict__ Q,
                                               const float* __restrict__ Kr,
                                               const float* __restrict__ V,
                                               float* __restrict__ hc)
{
    extern __shared__ float sh[];
    float* Qs = sh;                    // [64][QST]
    float* Ps = Qs + 64*QST;           // [64][QST]
    float* Ks = Ps + 64*QST;           // [e][t] [64][KST]
    float* Vs = Ks + 64*KST;           // [t][e] [64][KST]

    int bh = blockIdx.y;
    int b = bh >> 4, h = bh & 15;
    int m0 = blockIdx.x << 6;
    const float* Qbh = Q  + (size_t)bh * SQ * DHQ;
    const float* Kbh = Kr + (size_t)bh * DHQ * SQ;
    const float* Vbh = V  + (size_t)bh * SQ * DHQ;

    int tid = threadIdx.x, wid = tid >> 5, lane = tid & 31;
    int grp = lane >> 2, tig = lane & 3;
    int mr = wid*16 + grp;

    // load Q tile
    for (int i = tid; i < 64*16; i += 128){
        int r = i >> 4, c4 = i & 15;
        *(float4*)&Qs[r*QST + c4*4] = *(const float4*)&Qbh[(size_t)(m0 + r) * DHQ + c4*4];
    }
    __syncthreads();

    // Q fragments (reused across all chunks)
    uint32_t aq[8][4];
    #pragma unroll
    for (int ks = 0; ks < 8; ks++){
        int kk = ks << 3;
        aq[ks][0] = __float_as_uint(Qs[mr*QST     + kk + tig]);
        aq[ks][1] = __float_as_uint(Qs[(mr+8)*QST + kk + tig]);
        aq[ks][2] = __float_as_uint(Qs[mr*QST     + kk + tig + 4]);
        aq[ks][3] = __float_as_uint(Qs[(mr+8)*QST + kk + tig + 4]);
    }

    float accO[8][4];
    #pragma unroll
    for (int nt = 0; nt < 8; nt++)
        #pragma unroll
        for (int q = 0; q < 4; q++) accO[nt][q] = 0.f;
    float mrow0 = -1e30f, mrow1 = -1e30f, lrow0 = 0.f, lrow1 = 0.f;
    const float scale = 1.0f / 1024.0f;

    for (int n0 = 0; n0 < SQ; n0 += 64){
        // load K,V chunk
        for (int i = tid; i < 64*16; i += 128){
            int r = i >> 4, c4 = i & 15;
            *(float4*)&Ks[r*KST + c4*4] = *(const float4*)&Kbh[(size_t)r * SQ + n0 + c4*4];
            *(float4*)&Vs[r*KST + c4*4] = *(const float4*)&Vbh[(size_t)(n0 + r) * DHQ + c4*4];
        }
        __syncthreads();

        // S = Q @ K (k = e)
        float sacc[8][4];
        #pragma unroll
        for (int nt = 0; nt < 8; nt++)
            #pragma unroll
            for (int q = 0; q < 4; q++) sacc[nt][q] = 0.f;
        #pragma unroll
        for (int ks = 0; ks < 8; ks++){
            int kk = ks << 3;
            uint32_t bf[8][2];
            #pragma unroll
            for (int nt = 0; nt < 8; nt++){
                int nr = nt*8 + grp;
                bf[nt][0] = __float_as_uint(Ks[(kk + tig)*KST     + nr]);
                bf[nt][1] = __float_as_uint(Ks[(kk + tig + 4)*KST + nr]);
            }
            #pragma unroll
            for (int nt = 0; nt < 8; nt++)
                mma_tf32(sacc[nt], aq[ks], bf[nt]);
        }

        // online softmax (rows grp, grp+8)
        float mx0 = -1e30f, mx1 = -1e30f;
        #pragma unroll
        for (int nt = 0; nt < 8; nt++){
            sacc[nt][0] *= scale; sacc[nt][1] *= scale;
            sacc[nt][2] *= scale; sacc[nt][3] *= scale;
            mx0 = fmaxf(mx0, fmaxf(sacc[nt][0], sacc[nt][1]));
            mx1 = fmaxf(mx1, fmaxf(sacc[nt][2], sacc[nt][3]));
        }
        mx0 = fmaxf(mx0, __shfl_xor_sync(0xffffffffu, mx0, 1));
        mx0 = fmaxf(mx0, __shfl_xor_sync(0xffffffffu, mx0, 2));
        mx1 = fmaxf(mx1, __shfl_xor_sync(0xffffffffu, mx1, 1));
        mx1 = fmaxf(mx1, __shfl_xor_sync(0xffffffffu, mx1, 2));
        float mn0 = fmaxf(mrow0, mx0), mn1 = fmaxf(mrow1, mx1);
        float al0 = __expf(mrow0 - mn0), al1 = __expf(mrow1 - mn1);
        mrow0 = mn0; mrow1 = mn1;

        float ps0 = 0.f, ps1 = 0.f;
        #pragma unroll
        for (int nt = 0; nt < 8; nt++){
            float p0 = __expf(sacc[nt][0] - mn0);
            float p1 = __expf(sacc[nt][1] - mn0);
            float p2 = __expf(sacc[nt][2] - mn1);
            float p3 = __expf(sacc[nt][3] - mn1);
            ps0 += p0 + p1; ps1 += p2 + p3;
            int col = nt*8 + tig*2;
            *(float2*)&Ps[mr*QST + col]     = make_float2(rnd_tf32(p0), rnd_tf32(p1));
            *(float2*)&Ps[(mr+8)*QST + col] = make_float2(rnd_tf32(p2), rnd_tf32(p3));
        }
        ps0 += __shfl_xor_sync(0xffffffffu, ps0, 1);
        ps0 += __shfl_xor_sync(0xffffffffu, ps0, 2);
        ps1 += __shfl_xor_sync(0xffffffffu, ps1, 1);
        ps1 += __shfl_xor_sync(0xffffffffu, ps1, 2);
        lrow0 = lrow0 * al0 + ps0;
        lrow1 = lrow1 * al1 + ps1;
        #pragma unroll
        for (int nt = 0; nt < 8; nt++){
            accO[nt][0] *= al0; accO[nt][1] *= al0;
            accO[nt][2] *= al1; accO[nt][3] *= al1;
        }
        __syncwarp();

        // O += P @ V (k = t, n = e)
        #pragma unroll
        for (int ks = 0; ks < 8; ks++){
            int kk = ks << 3;
            uint32_t ap[4], bf[8][2];
            ap[0] = __float_as_uint(Ps[mr*QST     + kk + tig]);
            ap[1] = __float_as_uint(Ps[(mr+8)*QST + kk + tig]);
            ap[2] = __float_as_uint(Ps[mr*QST     + kk + tig + 4]);
            ap[3] = __float_as_uint(Ps[(mr+8)*QST + kk + tig + 4]);
            #pragma unroll
            for (int nt = 0; nt < 8; nt++){
                int nr = nt*8 + grp;
                bf[nt][0] = __float_as_uint(Vs[(kk + tig)*KST     + nr]);
                bf[nt][1] = __float_as_uint(Vs[(kk + tig + 4)*KST + nr]);
            }
            #pragma unroll
            for (int nt = 0; nt < 8; nt++)
                mma_tf32(accO[nt], ap, bf[nt]);
        }
        __syncthreads();   // all warps done with Ks/Vs before next chunk overwrites
    }

    // write heads in concat layout [B, S, H*DH], rounded (feeds O-proj GEMM)
    float inv0 = 1.0f / lrow0, inv1 = 1.0f / lrow1;
    int row0 = m0 + mr, row1 = row0 + 8;
    #pragma unroll
    for (int nt = 0; nt < 8; nt++){
        int e = nt*8 + tig*2;
        *(float2*)&hc[((size_t)b*SQ + row0)*DQ + h*64 + e] =
            make_float2(rnd_tf32(accO[nt][0]*inv0), rnd_tf32(accO[nt][1]*inv0));
        *(float2*)&hc[((size_t)b*SQ + row1)*DQ + h*64 + e] =
            make_float2(rnd_tf32(accO[nt][2]*inv1), rnd_tf32(accO[nt][3]*inv1));
    }
}

// ---------------- launch ----------------
extern "C" void kernel_launch(void* const* d_in, const int* in_sizes, int n_in,
                              void* d_out, int out_size)
{
    const float* x      = (const float*)d_in[0];
    const float* W_Q    = (const float*)d_in[1];
    const float* W_K    = (const float*)d_in[2];
    const float* W_V    = (const float*)d_in[3];
    const float* W_O    = (const float*)d_in[4];
    const float* W_up   = (const float*)d_in[5];
    const float* b_up   = (const float*)d_in[6];
    const float* W_down = (const float*)d_in[7];
    const float* b_down = (const float*)d_in[8];
    const float* gamma1 = (const float*)d_in[9];
    const float* beta1  = (const float*)d_in[10];
    const float* gamma2 = (const float*)d_in[11];
    const float* beta2  = (const float*)d_in[12];
    float* out = (float*)d_out;

    float *u, *Qp, *Krp, *Vp, *hcp, *z1, *v1, *v3, *WOt, *Wupt, *Wdnt, *WQr, *WKr, *WVr;
    cudaGetSymbolAddress((void**)&u,    g_u);
    cudaGetSymbolAddress((void**)&Qp,   g_Q);
    cudaGetSymbolAddress((void**)&Krp,  g_Kr);
    cudaGetSymbolAddress((void**)&Vp,   g_V);
    cudaGetSymbolAddress((void**)&hcp,  g_hc);
    cudaGetSymbolAddress((void**)&z1,   g_z1);
    cudaGetSymbolAddress((void**)&v1,   g_v1);
    cudaGetSymbolAddress((void**)&v3,   g_v3);
    cudaGetSymbolAddress((void**)&WOt,  g_WOt);
    cudaGetSymbolAddress((void**)&Wupt, g_Wupt);
    cudaGetSymbolAddress((void**)&Wdnt, g_Wdnt);
    cudaGetSymbolAddress((void**)&WQr,  g_WQr);
    cudaGetSymbolAddress((void**)&WKr,  g_WKr);
    cudaGetSymbolAddress((void**)&WVr,  g_WVr);

    cudaFuncSetAttribute((const void*)mma_gemm<1>, cudaFuncAttributeMaxDynamicSharedMemorySize, GEMM_SMEM);
    cudaFuncSetAttribute((const void*)mma_gemm<2>, cudaFuncAttributeMaxDynamicSharedMemorySize, GEMM_SMEM);
    cudaFuncSetAttribute((const void*)mma_gemm<3>, cudaFuncAttributeMaxDynamicSharedMemorySize, GEMM_SMEM);
    cudaFuncSetAttribute((const void*)mma_gemm<4>, cudaFuncAttributeMaxDynamicSharedMemorySize, GEMM_SMEM);
    cudaFuncSetAttribute((const void*)mma_gemm<5>, cudaFuncAttributeMaxDynamicSharedMemorySize, GEMM_SMEM);
    cudaFuncSetAttribute((const void*)attn_tc,     cudaFuncAttributeMaxDynamicSharedMemorySize, ATTN_SMEM);

    // weight prep (tf32-rounded)
    transpose_kernel<<<dim3(DQ/32, DQ/32), dim3(32,8)>>>(W_O,    WOt,  DQ, DQ);
    transpose_kernel<<<dim3(FQ/32, DQ/32), dim3(32,8)>>>(W_up,   Wupt, DQ, FQ);
    transpose_kernel<<<dim3(DQ/32, FQ/32), dim3(32,8)>>>(W_down, Wdnt, FQ, DQ);
    round_copy_kernel<<<1024, 256>>>(W_Q, WQr, DQ*DQ/4);
    round_copy_kernel<<<1024, 256>>>(W_K, WKr, DQ*DQ/4);
    round_copy_kernel<<<1024, 256>>>(W_V, WVr, DQ*DQ/4);

    // 1. LN1 (rounded: feeds QKV GEMMs)
    ln_kernel<1><<<MQ, 256>>>(x, gamma1, beta1, u);
    // 2. QKV projections, scatter epilogues (rounded: feed attention)
    mma_gemm<4><<<dim3(DQ/128, MQ/256), 256, GEMM_SMEM>>>(u, WQr, Qp,  MQ, DQ, DQ, nullptr, nullptr);
    mma_gemm<5><<<dim3(DQ/128, MQ/256), 256, GEMM_SMEM>>>(u, WKr, Krp, MQ, DQ, DQ, nullptr, nullptr);
    mma_gemm<4><<<dim3(DQ/128, MQ/256), 256, GEMM_SMEM>>>(u, WVr, Vp,  MQ, DQ, DQ, nullptr, nullptr);
    // 3. tensor-core flash attention
    attn_tc<<<dim3(SQ/64, BQ*HQ), 128, ATTN_SMEM>>>(Qp, Krp, Vp, hcp);
    // 4. O projection + residual x (fp32 out)
    mma_gemm<1><<<dim3(DQ/128, MQ/256), 256, GEMM_SMEM>>>(hcp, WOt, z1, MQ, DQ, DQ, nullptr, x);
    // 5. LN2 (rounded: feeds FFN-up)
    ln_kernel<1><<<MQ, 256>>>(z1, gamma2, beta2, v1);
    // 6. FFN up + bias + exact GELU (rounded: feeds FFN-down)
    mma_gemm<2><<<dim3(FQ/128, MQ/256), 256, GEMM_SMEM>>>(v1, Wupt, v3, MQ, FQ, DQ, b_up, nullptr);
    // 7. FFN down + bias + residual z1 -> out (fp32)
    mma_gemm<3><<<dim3(DQ/128, MQ/256), 256, GEMM_SMEM>>>(v3, Wdnt, out, MQ, DQ, FQ, b_down, z1);
}